// round 2
// baseline (speedup 1.0000x reference)
#include <cuda_runtime.h>
#include <math.h>

#define NROWS 6144
#define KDIM  128
#define NCLS  200
#define RPB   8
#define NBLK  (NROWS / RPB)      // 768
#define NTHR  256
#define SIMCAP 2048
#define QBLKS 192

// smem layout byte offsets
#define SM_ROWS   0
#define SM_UHI    (SM_ROWS + RPB*NROWS*4)          // 196608
#define SM_SLAB   (SM_UHI + RPB*KDIM*4)            // 200704
#define SM_HIST   (SM_SLAB + NROWS)                // 206848
#define SM_SIMV   (SM_HIST + 256*4)                // 207872
#define SM_RF     (SM_SIMV + SIMCAP*4)             // 216064
#define SM_RI     (SM_RF + 16*4)                   // 216128
#define SM_SCRF   (SM_RI + 16*4)                   // 216192
#define SM_SCRI   (SM_SCRF + 32*4)                 // 216320
#define SMEM_BYTES (SM_SCRI + 32*4)                // 216448

static __device__ float g_uh[NROWS * KDIM];
static __device__ int   g_label[NROWS];
static __device__ float g_rowpos[NROWS];
static __device__ float g_rowneg[NROWS];
static __device__ int   g_valid[NROWS];
static __device__ float g_qpart[QBLKS];

__device__ __forceinline__ unsigned f2key(float f) {
    unsigned u = __float_as_uint(f);
    return (u & 0x80000000u) ? ~u : (u | 0x80000000u);
}
__device__ __forceinline__ float key2f(unsigned k) {
    unsigned u = (k & 0x80000000u) ? (k ^ 0x80000000u) : ~k;
    return __uint_as_float(u);
}
__device__ __forceinline__ float clip64(float x) { return fminf(fmaxf(x, 0.f), 64.f); }
__device__ __forceinline__ float softplus_f(float x) {
    return fmaxf(x, 0.f) + __logf(1.f + __expf(-fabsf(x)));
}

// Deterministic block reduction (fixed shfl tree order).
__device__ __forceinline__ float blockSum(float v, float* scr) {
    #pragma unroll
    for (int o = 16; o > 0; o >>= 1) v += __shfl_xor_sync(0xFFFFFFFFu, v, o);
    __syncthreads();
    if ((threadIdx.x & 31) == 0) scr[threadIdx.x >> 5] = v;
    __syncthreads();
    if (threadIdx.x < 32) {
        float x = (threadIdx.x < (NTHR >> 5)) ? scr[threadIdx.x] : 0.f;
        #pragma unroll
        for (int o = 4; o > 0; o >>= 1) x += __shfl_xor_sync(0xFFFFFFFFu, x, o);
        if (threadIdx.x == 0) scr[0] = x;
    }
    __syncthreads();
    return scr[0];
}
__device__ __forceinline__ int blockSumI(int v, int* scr) {
    #pragma unroll
    for (int o = 16; o > 0; o >>= 1) v += __shfl_xor_sync(0xFFFFFFFFu, v, o);
    __syncthreads();
    if ((threadIdx.x & 31) == 0) scr[threadIdx.x >> 5] = v;
    __syncthreads();
    if (threadIdx.x < 32) {
        int x = (threadIdx.x < (NTHR >> 5)) ? scr[threadIdx.x] : 0;
        #pragma unroll
        for (int o = 4; o > 0; o >>= 1) x += __shfl_xor_sync(0xFFFFFFFFu, x, o);
        if (threadIdx.x == 0) scr[0] = x;
    }
    __syncthreads();
    return scr[0];
}

// ---------------- kernel 0: tanh + quantization-loss partials -----------------
__global__ void __launch_bounds__(NTHR) tanh_kernel(const float* __restrict__ u) {
    __shared__ float scr[32];
    float q = 0.f;
    for (int t = blockIdx.x * blockDim.x + threadIdx.x; t < NROWS * KDIM;
         t += gridDim.x * blockDim.x) {
        float x = tanhf(u[t]);
        g_uh[t] = x;
        float s = (x > 0.f) ? 1.f : ((x < 0.f) ? -1.f : 0.f);
        float d = x - s;
        q += d * d;
    }
    float bs = blockSum(q, scr);
    if (threadIdx.x == 0) g_qpart[blockIdx.x] = bs;
}

// ---------------- kernel 1: one-hot -> label ---------------------------------
__global__ void label_kernel(const int* __restrict__ y) {
    int i = blockIdx.x * blockDim.x + threadIdx.x;
    if (i < NROWS) {
        int lab = 0;
        const int* yr = y + (size_t)i * NCLS;
        for (int c = 0; c < NCLS; c++) {
            if (yr[c] != 0) { lab = c; break; }
        }
        g_label[i] = lab;
    }
}

// ---------------- kernel 2: fused inner-product + stats + loss ---------------
__global__ void __launch_bounds__(NTHR, 1) stats_loss_kernel() {
    extern __shared__ unsigned char sm[];
    float* rows         = (float*)(sm + SM_ROWS);   // [RPB][NROWS]
    float* uhi          = (float*)(sm + SM_UHI);    // [RPB][KDIM]
    unsigned char* slab = (unsigned char*)(sm + SM_SLAB);
    int*   hist         = (int*)(sm + SM_HIST);
    float* simv         = (float*)(sm + SM_SIMV);
    float* rf           = (float*)(sm + SM_RF);
    int*   ri           = (int*)(sm + SM_RI);
    float* scrF         = (float*)(sm + SM_SCRF);
    int*   scrI         = (int*)(sm + SM_SCRI);

    const int tid = threadIdx.x;
    const int i0  = blockIdx.x * RPB;

    for (int t = tid; t < RPB * KDIM; t += NTHR) uhi[t] = g_uh[i0 * KDIM + t];
    for (int t = tid; t < NROWS; t += NTHR) slab[t] = (unsigned char)g_label[t];
    __syncthreads();

    // ---- Phase B: inner[i0..i0+7][:] into shared, packed f32x2 FMA ----
    for (int j = tid; j < NROWS; j += NTHR) {
        unsigned long long acc[RPB];
        #pragma unroll
        for (int r = 0; r < RPB; r++) acc[r] = 0ull;
        const ulonglong2* up = (const ulonglong2*)(g_uh + (size_t)j * KDIM);
        const ulonglong2* wp = (const ulonglong2*)uhi;
        #pragma unroll 4
        for (int kk = 0; kk < KDIM / 4; kk++) {
            ulonglong2 v = up[kk];
            #pragma unroll
            for (int r = 0; r < RPB; r++) {
                ulonglong2 w = wp[r * (KDIM / 4) + kk];
                asm("fma.rn.f32x2 %0, %1, %2, %0;" : "+l"(acc[r]) : "l"(v.x), "l"(w.x));
                asm("fma.rn.f32x2 %0, %1, %2, %0;" : "+l"(acc[r]) : "l"(v.y), "l"(w.y));
            }
        }
        #pragma unroll
        for (int r = 0; r < RPB; r++) {
            float lo = __uint_as_float((unsigned)(acc[r] & 0xFFFFFFFFull));
            float hi = __uint_as_float((unsigned)(acc[r] >> 32));
            rows[r * NROWS + j] = lo + hi;
        }
    }
    __syncthreads();

    // ---- Phase C: per-row stats, selections, losses ----
    for (int r = 0; r < RPB; r++) {
        const int irow = i0 + r;
        const unsigned char labi = slab[irow];
        const float* row = rows + r * NROWS;

        // pass 1: sums + collect similar values
        if (tid == 0) ri[0] = 0;
        __syncthreads();
        float lS = 0.f, lD = 0.f; int lns = 0;
        for (int j = tid; j < NROWS; j += NTHR) {
            float v = row[j];
            if (slab[j] == labi) {
                lS += v; lns++;
                int p = atomicAdd(&ri[0], 1);
                if (p < SIMCAP) simv[p] = v;
            } else {
                lD += v;
            }
        }
        float sumS = blockSum(lS, scrF);
        float sumD = blockSum(lD, scrF);
        int nsim   = blockSumI(lns, scrI);
        int ndis   = NROWS - nsim;

        // sMin: mean of the m smallest similar values (deterministic: sorted order)
        if (tid == 0) {
            int cnt = min(nsim, SIMCAP);
            int m = nsim - (nsim * 9) / 10;
            if (m < 1) m = 1;
            float ssum = 0.f;
            for (int it = 0; it < m && it < cnt; it++) {
                int bi = it; float bv = simv[it];
                for (int t2 = it + 1; t2 < cnt; t2++) {
                    float x = simv[t2];
                    if (x < bv) { bv = x; bi = t2; }
                }
                simv[bi] = simv[it]; simv[it] = bv;
                ssum += bv;
            }
            rf[0] = clip64(ssum / (float)max(m, 1));   // sMin
        }

        // dMax: exact top-k dissimilar via 4-pass radix select on float keys
        int ksel = ndis - (ndis * 9) / 10;
        if (ksel < 1) ksel = 1;
        unsigned prefix = 0;
        int kk = ksel;
        if (ndis > 0) {
            for (int p = 0; p < 4; p++) {
                int shift = 24 - 8 * p;
                for (int t = tid; t < 256; t += NTHR) hist[t] = 0;
                __syncthreads();
                for (int j = tid; j < NROWS; j += NTHR) {
                    if (slab[j] != labi) {
                        unsigned key = f2key(row[j]);
                        if (p == 0 || (key >> (shift + 8)) == prefix)
                            atomicAdd(&hist[(key >> shift) & 255], 1);
                    }
                }
                __syncthreads();
                if (tid == 0) {
                    int cum = 0; int b = 255;
                    for (; b > 0; b--) {
                        int c = hist[b];
                        if (cum + c >= kk) break;
                        cum += c;
                    }
                    ri[1] = b; ri[2] = kk - cum;
                }
                __syncthreads();
                prefix = (prefix << 8) | (unsigned)ri[1];
                kk = ri[2];
                __syncthreads();
            }
        }
        float tval = key2f(prefix);
        float lg = 0.f; int lc = 0;
        if (ndis > 0) {
            for (int j = tid; j < NROWS; j += NTHR) {
                if (slab[j] != labi) {
                    float v = row[j];
                    if (f2key(v) > prefix) { lg += v; lc++; }
                }
            }
        }
        float sgt = blockSum(lg, scrF);
        int   cgt = blockSumI(lc, scrI);

        if (tid == 0) {
            float dMax = 0.f;
            if (ndis > 0) {
                float dsum = sgt + (float)(ksel - cgt) * tval;  // tie correction
                dMax = clip64(dsum / (float)max(ksel, 1));
            }
            float meanS  = clip64(sumS / fmaxf((float)nsim, 1.f));
            float meanDS = clip64(sumD / fmaxf((float)ndis, 1.f));
            float sMin = rf[0];
            float BP  = meanS  - (64.f - meanS) / 64.f * fabsf(meanS - dMax);
            float BPd = meanDS + meanDS / 64.f * fabsf(meanDS - sMin);
            rf[1] = BP; rf[2] = BPd;
        }
        __syncthreads();
        float BP = rf[1], BPd = rf[2];

        // loss pass (A_COEF == 2 exactly; C_COEF = -ln(99)/16)
        const float C1 = -0.2871949906334119f;
        const float C2 = 2.f * C1;
        float lp = 0.f, lnv = 0.f; int lcp = 0, lcn = 0;
        for (int j = tid; j < NROWS; j += NTHR) {
            float v = row[j];
            if (slab[j] == labi) {
                if (v != BP) {
                    float dc = v - BP;
                    float f = (v > BP) ? C1 * dc : C2 * dc;
                    lp += softplus_f(f); lcp++;
                }
            } else {
                if (v != BPd) {
                    float dc = v - BPd;
                    float f = (v < BPd) ? C1 * dc : C2 * dc;
                    lnv += softplus_f(-f); lcn++;
                }
            }
        }
        float posS = blockSum(lp, scrF);
        float negS = blockSum(lnv, scrF);
        int cp = blockSumI(lcp, scrI);
        int cn = blockSumI(lcn, scrI);
        if (tid == 0) {
            g_rowpos[irow] = posS / fmaxf((float)cp, 1.f);
            g_rowneg[irow] = negS / fmaxf((float)cn, 1.f);
            g_valid[irow]  = (nsim > 0 && ndis > 0) ? 1 : 0;
        }
        __syncthreads();
    }
}

// ---------------- kernel 3: final scalar -------------------------------------
__global__ void __launch_bounds__(NTHR) final_kernel(float* __restrict__ out) {
    __shared__ float scrF[32];
    __shared__ int scrI[32];
    int tid = threadIdx.x;
    float ps = 0.f, ns = 0.f; int cv = 0;
    for (int i = tid; i < NROWS; i += NTHR) {
        if (g_valid[i]) { ps += g_rowpos[i]; ns += g_rowneg[i]; cv++; }
    }
    float psum = blockSum(ps, scrF);
    float nsum = blockSum(ns, scrF);
    int cnt = blockSumI(cv, scrI);
    float q = 0.f;
    for (int i = tid; i < QBLKS; i += NTHR) q += g_qpart[i];
    float qs = blockSum(q, scrF);
    if (tid == 0) {
        float posL = (cnt > 0) ? psum / fmaxf((float)cnt, 1.f) : 0.f;
        float navL = (cnt > 0) ? nsum / fmaxf((float)cnt, 1.f) : 0.f;
        float ql = 0.1f * qs / (float)(NROWS * KDIM);
        out[0] = posL + navL + ql;
    }
}

extern "C" void kernel_launch(void* const* d_in, const int* in_sizes, int n_in,
                              void* d_out, int out_size) {
    const float* u = (const float*)d_in[0];
    const int*   y = (const int*)d_in[1];
    (void)in_sizes; (void)n_in; (void)out_size;

    cudaFuncSetAttribute(stats_loss_kernel,
                         cudaFuncAttributeMaxDynamicSharedMemorySize, SMEM_BYTES);

    tanh_kernel<<<QBLKS, NTHR>>>(u);
    label_kernel<<<(NROWS + 255) / 256, 256>>>(y);
    stats_loss_kernel<<<NBLK, NTHR, SMEM_BYTES>>>();
    final_kernel<<<1, NTHR>>>((float*)d_out);
}

// round 3
// speedup vs baseline: 3.4863x; 3.4863x over previous
#include <cuda_runtime.h>
#include <math.h>

#define NROWS 6144
#define KDIM  128
#define NCLS  200
#define RPB   8
#define NBLK  (NROWS / RPB)      // 768
#define NTHR  512
#define NWARP (NTHR / 32)        // 16
#define SIMCAP 128
#define QBLKS 192

// ---- shared memory layout (byte offsets) ----
#define SM_ROWS   0                                   // [8][6144] f32  = 196608
#define SM_UHIP   (SM_ROWS + RPB*NROWS*4)             // [8][128] u64   = 8192  -> 204800
#define SM_SLAB   (SM_UHIP + RPB*KDIM*8)              // 6144 bytes     -> 210944
#define SM_HIST   (SM_SLAB + NROWS)                   // [8][256] int   -> 219136
#define SM_SIMV   (SM_HIST + RPB*256*4)               // [8][128] f32   -> 223232
#define SM_SCNT   (SM_SIMV + RPB*SIMCAP*4)            // [8] int        -> 223264
#define SM_MISC   (SM_SCNT + RPB*4)                   // misc arrays
// misc: sumS[8] sumD[8] sgt[8] sMin[8] BP[8] BPd[8] (float), nsim[8] ksel[8] kk[8] prefix[8] cgt[8] (int)
#define MISC_SUMS  (SM_MISC + 0)
#define MISC_SUMD  (SM_MISC + 32)
#define MISC_SGT   (SM_MISC + 64)
#define MISC_SMIN  (SM_MISC + 96)
#define MISC_BP    (SM_MISC + 128)
#define MISC_BPD   (SM_MISC + 160)
#define MISC_NSIM  (SM_MISC + 192)
#define MISC_KSEL  (SM_MISC + 224)
#define MISC_KK    (SM_MISC + 256)
#define MISC_PFX   (SM_MISC + 288)
#define MISC_CGT   (SM_MISC + 320)
#define MISC_EP    (SM_MISC + 352)
#define MISC_EN    (SM_MISC + 384)
#define MISC_LP    (SM_MISC + 416)
#define MISC_LN    (SM_MISC + 448)
#define SM_WSCR   (SM_MISC + 512)                     // [16][8] f32/int = 512 B
#define SMEM_BYTES (SM_WSCR + NWARP*8*4)              // 224288

static __device__ float g_uhT[KDIM * NROWS];   // transposed tanh(u): [k][j]
static __device__ int   g_label[NROWS];
static __device__ float g_rowpos[NROWS];
static __device__ float g_rowneg[NROWS];
static __device__ int   g_valid[NROWS];
static __device__ float g_qpart[QBLKS];

__device__ __forceinline__ unsigned f2key(float f) {
    unsigned u = __float_as_uint(f);
    return (u & 0x80000000u) ? ~u : (u | 0x80000000u);
}
__device__ __forceinline__ float key2f(unsigned k) {
    unsigned u = (k & 0x80000000u) ? (k ^ 0x80000000u) : ~k;
    return __uint_as_float(u);
}
__device__ __forceinline__ float clip64(float x) { return fminf(fmaxf(x, 0.f), 64.f); }
__device__ __forceinline__ float softplus_f(float x) {
    return fmaxf(x, 0.f) + __logf(1.f + __expf(-fabsf(x)));
}
__device__ __forceinline__ unsigned long long packww(float w) {
    unsigned long long r;
    asm("mov.b64 %0, {%1, %1};" : "=l"(r) : "f"(w));
    return r;
}

// deterministic 8-value block reductions (fixed order)
__device__ __forceinline__ void blockSum8F(float v[8], float* wscr, float* out8,
                                           int tid) {
    int lane = tid & 31, wid = tid >> 5;
    #pragma unroll
    for (int r = 0; r < 8; r++) {
        #pragma unroll
        for (int o = 16; o > 0; o >>= 1) v[r] += __shfl_xor_sync(0xFFFFFFFFu, v[r], o);
    }
    if (lane == 0) {
        #pragma unroll
        for (int r = 0; r < 8; r++) wscr[wid * 8 + r] = v[r];
    }
    __syncthreads();
    if (tid < 8) {
        float s = 0.f;
        #pragma unroll
        for (int w = 0; w < NWARP; w++) s += wscr[w * 8 + tid];
        out8[tid] = s;
    }
    __syncthreads();
}
__device__ __forceinline__ void blockSum8I(int v[8], int* wscr, int* out8, int tid) {
    int lane = tid & 31, wid = tid >> 5;
    #pragma unroll
    for (int r = 0; r < 8; r++) {
        #pragma unroll
        for (int o = 16; o > 0; o >>= 1) v[r] += __shfl_xor_sync(0xFFFFFFFFu, v[r], o);
    }
    if (lane == 0) {
        #pragma unroll
        for (int r = 0; r < 8; r++) wscr[wid * 8 + r] = v[r];
    }
    __syncthreads();
    if (tid < 8) {
        int s = 0;
        #pragma unroll
        for (int w = 0; w < NWARP; w++) s += wscr[w * 8 + tid];
        out8[tid] = s;
    }
    __syncthreads();
}

// ---------------- kernel 0: tanh + quantization partials + transpose ----------
__global__ void __launch_bounds__(256) tanh_kernel(const float* __restrict__ u) {
    __shared__ float tile[32][129];
    __shared__ float scr[8];
    const int tid = threadIdx.x;
    const int i0 = blockIdx.x * 32;
    float q = 0.f;
    for (int idx = tid; idx < 32 * KDIM; idx += 256) {
        int r = idx >> 7, k = idx & 127;
        float x = tanhf(u[(i0 + r) * KDIM + k]);
        tile[r][k] = x;
        float s = (x > 0.f) ? 1.f : ((x < 0.f) ? -1.f : 0.f);
        float d = x - s;
        q += d * d;
    }
    __syncthreads();
    for (int idx = tid; idx < 32 * KDIM; idx += 256) {
        int k = idx >> 5, i = idx & 31;
        g_uhT[k * NROWS + i0 + i] = tile[i][k];
    }
    // reduce q
    #pragma unroll
    for (int o = 16; o > 0; o >>= 1) q += __shfl_xor_sync(0xFFFFFFFFu, q, o);
    if ((tid & 31) == 0) scr[tid >> 5] = q;
    __syncthreads();
    if (tid == 0) {
        float s = 0.f;
        for (int w = 0; w < 8; w++) s += scr[w];
        g_qpart[blockIdx.x] = s;
    }
}

// ---------------- kernel 1: one-hot -> label ---------------------------------
__global__ void label_kernel(const int* __restrict__ y) {
    int i = blockIdx.x * blockDim.x + threadIdx.x;
    if (i < NROWS) {
        int lab = 0;
        const int* yr = y + (size_t)i * NCLS;
        for (int c = 0; c < NCLS; c++) {
            if (yr[c] != 0) { lab = c; break; }
        }
        g_label[i] = lab;
    }
}

// ---------------- kernel 2: fused inner-product + stats + loss ---------------
__global__ void __launch_bounds__(NTHR, 1) stats_loss_kernel() {
    extern __shared__ unsigned char sm[];
    float* rows               = (float*)(sm + SM_ROWS);
    unsigned long long* uhiP  = (unsigned long long*)(sm + SM_UHIP);
    unsigned char* slab       = (unsigned char*)(sm + SM_SLAB);
    int*   hist               = (int*)(sm + SM_HIST);
    float* simv               = (float*)(sm + SM_SIMV);
    int*   scnt               = (int*)(sm + SM_SCNT);
    float* sumS8              = (float*)(sm + MISC_SUMS);
    float* sumD8              = (float*)(sm + MISC_SUMD);
    float* sgt8               = (float*)(sm + MISC_SGT);
    float* sMin8              = (float*)(sm + MISC_SMIN);
    float* BP8                = (float*)(sm + MISC_BP);
    float* BPd8               = (float*)(sm + MISC_BPD);
    int*   nsim8              = (int*)(sm + MISC_NSIM);
    int*   ksel8              = (int*)(sm + MISC_KSEL);
    int*   kk8                = (int*)(sm + MISC_KK);
    unsigned* pfx8            = (unsigned*)(sm + MISC_PFX);
    int*   cgt8               = (int*)(sm + MISC_CGT);
    int*   ep8                = (int*)(sm + MISC_EP);
    int*   en8                = (int*)(sm + MISC_EN);
    float* lp8                = (float*)(sm + MISC_LP);
    float* ln8                = (float*)(sm + MISC_LN);
    float* wscrF              = (float*)(sm + SM_WSCR);
    int*   wscrI              = (int*)(sm + SM_WSCR);

    const int tid = threadIdx.x;
    const int i0  = blockIdx.x * RPB;

    // ---- load packed (w,w) weights and labels ----
    for (int t = tid; t < RPB * KDIM; t += NTHR) {
        int r = t >> 7, k = t & 127;
        uhiP[r * KDIM + k] = packww(g_uhT[k * NROWS + i0 + r]);
    }
    for (int t = tid; t < NROWS; t += NTHR) slab[t] = (unsigned char)g_label[t];
    // zero hist + scnt for phase C pass 0 (done now, synced below)
    for (int t = tid; t < RPB * 256; t += NTHR) hist[t] = 0;
    if (tid < RPB) scnt[tid] = 0;
    __syncthreads();

    // ---- Phase B: coalesced GEMM slab, f32x2 lanes = j-pairs ----
    #pragma unroll
    for (int tile = 0; tile < 3; tile++) {
        const int j0 = (tid + tile * NTHR) * 4;
        unsigned long long a0[RPB], a1[RPB];
        #pragma unroll
        for (int r = 0; r < RPB; r++) { a0[r] = 0ull; a1[r] = 0ull; }
        #pragma unroll 4
        for (int k = 0; k < KDIM; k++) {
            ulonglong2 v = *(const ulonglong2*)(g_uhT + (size_t)k * NROWS + j0);
            #pragma unroll
            for (int r = 0; r < RPB; r++) {
                unsigned long long w = uhiP[r * KDIM + k];
                asm("fma.rn.f32x2 %0, %1, %2, %0;" : "+l"(a0[r]) : "l"(v.x), "l"(w));
                asm("fma.rn.f32x2 %0, %1, %2, %0;" : "+l"(a1[r]) : "l"(v.y), "l"(w));
            }
        }
        #pragma unroll
        for (int r = 0; r < RPB; r++) {
            ulonglong2 o; o.x = a0[r]; o.y = a1[r];
            *(ulonglong2*)(rows + r * NROWS + j0) = o;
        }
    }
    __syncthreads();

    // labels of our 8 rows, packed
    unsigned long long labi64 = 0;
    #pragma unroll
    for (int r = 0; r < RPB; r++)
        labi64 |= ((unsigned long long)slab[i0 + r]) << (8 * r);

    // ---- S1: sums, similar collection, radix pass-0 histogram ----
    {
        float sS[8], sD[8];
        #pragma unroll
        for (int r = 0; r < 8; r++) { sS[r] = 0.f; sD[r] = 0.f; }
        for (int j = tid; j < NROWS; j += NTHR) {
            unsigned lab = slab[j];
            #pragma unroll
            for (int r = 0; r < RPB; r++) {
                float v = rows[r * NROWS + j];
                bool sim = ((unsigned)(labi64 >> (8 * r)) & 255u) == lab;
                if (sim) {
                    sS[r] += v;
                    int p = atomicAdd(&scnt[r], 1);
                    if (p < SIMCAP) simv[r * SIMCAP + p] = v;
                } else {
                    sD[r] += v;
                    atomicAdd(&hist[r * 256 + (f2key(v) >> 24)], 1);
                }
            }
        }
        blockSum8F(sS, wscrF, sumS8, tid);
        blockSum8F(sD, wscrF, sumD8, tid);
    }
    __syncthreads();

    // ---- sMin (8-way parallel small selection) + radix init ----
    if (tid < RPB) {
        int r = tid;
        int ns = scnt[r];
        nsim8[r] = ns;
        int nd = NROWS - ns;
        int ks = nd - (nd * 9) / 10;
        if (ks < 1) ks = 1;
        ksel8[r] = ks;
        kk8[r]   = ks;
        pfx8[r]  = 0u;
        // sMin: mean of m smallest similar values
        int cnt = ns < SIMCAP ? ns : SIMCAP;
        int m = ns - (ns * 9) / 10;
        if (m < 1) m = 1;
        float* sv = simv + r * SIMCAP;
        float ssum = 0.f;
        for (int it = 0; it < m && it < cnt; it++) {
            int bi = it; float bv = sv[it];
            for (int t2 = it + 1; t2 < cnt; t2++) {
                float x = sv[t2];
                if (x < bv) { bv = x; bi = t2; }
            }
            sv[bi] = sv[it]; sv[it] = bv;
            ssum += bv;
        }
        sMin8[r] = clip64(ssum / (float)(m > 1 ? m : 1));
    }
    __syncthreads();

    // ---- radix select: 4 passes of 8 bits, merged across rows ----
    const int lane = tid & 31, wid = tid >> 5;
    #pragma unroll
    for (int p = 0; p < 4; p++) {
        if (p > 0) {
            int shift = 24 - 8 * p;
            for (int t = tid; t < RPB * 256; t += NTHR) hist[t] = 0;
            __syncthreads();
            for (int j = tid; j < NROWS; j += NTHR) {
                unsigned lab = slab[j];
                #pragma unroll
                for (int r = 0; r < RPB; r++) {
                    if ((((unsigned)(labi64 >> (8 * r)) & 255u) != lab)) {
                        unsigned key = f2key(rows[r * NROWS + j]);
                        if ((key >> (shift + 8)) == pfx8[r])
                            atomicAdd(&hist[r * 256 + ((key >> shift) & 255u)], 1);
                    }
                }
            }
            __syncthreads();
        }
        // warp-parallel reverse scan: warp r handles row r
        if (wid < RPB) {
            int r = wid;
            int kk = kk8[r];
            int csum = 0;
            int topbin = 255 - lane * 8;
            #pragma unroll
            for (int b = 0; b < 8; b++) csum += hist[r * 256 + topbin - b];
            int incl = csum;
            #pragma unroll
            for (int o = 1; o < 32; o <<= 1) {
                int t = __shfl_up_sync(0xFFFFFFFFu, incl, o);
                if (lane >= o) incl += t;
            }
            int excl = incl - csum;
            if (excl < kk && kk <= incl) {
                int running = excl;
                int bfound = 0, kknext = 0;
                #pragma unroll
                for (int b = 0; b < 8; b++) {
                    int bin = topbin - b;
                    int c = hist[r * 256 + bin];
                    running += c;
                    if (running >= kk) { bfound = bin; kknext = kk - (running - c); break; }
                }
                pfx8[r] = (pfx8[r] << 8) | (unsigned)bfound;
                kk8[r]  = kknext;
            }
        }
        __syncthreads();
    }

    // ---- S5: sum/count of dissimilar strictly above threshold ----
    {
        unsigned pf[8];
        #pragma unroll
        for (int r = 0; r < 8; r++) pf[r] = pfx8[r];
        float sg[8]; int cg[8];
        #pragma unroll
        for (int r = 0; r < 8; r++) { sg[r] = 0.f; cg[r] = 0; }
        for (int j = tid; j < NROWS; j += NTHR) {
            unsigned lab = slab[j];
            #pragma unroll
            for (int r = 0; r < RPB; r++) {
                if ((((unsigned)(labi64 >> (8 * r)) & 255u) != lab)) {
                    float v = rows[r * NROWS + j];
                    if (f2key(v) > pf[r]) { sg[r] += v; cg[r]++; }
                }
            }
        }
        blockSum8F(sg, wscrF, sgt8, tid);
        blockSum8I(cg, wscrI, cgt8, tid);
    }

    // ---- thresholds BP/BPd ----
    if (tid < RPB) {
        int r = tid;
        int ns = nsim8[r], nd = NROWS - ns;
        int ks = ksel8[r];
        float tval = key2f(pfx8[r]);
        float dsum = sgt8[r] + (float)(ks - cgt8[r]) * tval;
        float dMax = clip64(dsum / (float)(ks > 1 ? ks : 1));
        float meanS  = clip64(sumS8[r] / fmaxf((float)ns, 1.f));
        float meanDS = clip64(sumD8[r] / fmaxf((float)nd, 1.f));
        float sMin = sMin8[r];
        BP8[r]  = meanS  - (64.f - meanS) / 64.f * fabsf(meanS - dMax);
        BPd8[r] = meanDS + meanDS / 64.f * fabsf(meanDS - sMin);
    }
    __syncthreads();

    // ---- S6: loss sweep ----
    {
        const float C1 = -0.2871949906334119f;  // C_COEF = -ln(99)/16
        const float C2 = 2.f * C1;              // A_COEF * C_COEF (a == 2 exactly)
        float bp[8], bpd[8];
        #pragma unroll
        for (int r = 0; r < 8; r++) { bp[r] = BP8[r]; bpd[r] = BPd8[r]; }
        float lp[8], ln_[8]; int ep[8], en[8];
        #pragma unroll
        for (int r = 0; r < 8; r++) { lp[r] = 0.f; ln_[r] = 0.f; ep[r] = 0; en[r] = 0; }
        for (int j = tid; j < NROWS; j += NTHR) {
            unsigned lab = slab[j];
            #pragma unroll
            for (int r = 0; r < RPB; r++) {
                float v = rows[r * NROWS + j];
                bool sim = ((unsigned)(labi64 >> (8 * r)) & 255u) == lab;
                if (sim) {
                    if (v == bp[r]) ep[r]++;
                    else {
                        float dc = v - bp[r];
                        float f = (v > bp[r]) ? C1 * dc : C2 * dc;
                        lp[r] += softplus_f(f);
                    }
                } else {
                    if (v == bpd[r]) en[r]++;
                    else {
                        float dc = v - bpd[r];
                        float f = (v < bpd[r]) ? C1 * dc : C2 * dc;
                        ln_[r] += softplus_f(-f);
                    }
                }
            }
        }
        blockSum8F(lp, wscrF, lp8, tid);
        blockSum8F(ln_, wscrF, ln8, tid);
        blockSum8I(ep, wscrI, ep8, tid);
        blockSum8I(en, wscrI, en8, tid);
    }

    if (tid < RPB) {
        int r = tid;
        int ns = nsim8[r], nd = NROWS - ns;
        int cp = ns - ep8[r];
        int cn = nd - en8[r];
        g_rowpos[i0 + r] = lp8[r] / fmaxf((float)cp, 1.f);
        g_rowneg[i0 + r] = ln8[r] / fmaxf((float)cn, 1.f);
        g_valid[i0 + r]  = (ns > 0 && nd > 0) ? 1 : 0;
    }
}

// ---------------- kernel 3: final scalar -------------------------------------
__global__ void __launch_bounds__(256) final_kernel(float* __restrict__ out) {
    __shared__ float scrF[8];
    __shared__ int scrI[8];
    int tid = threadIdx.x;
    float ps = 0.f, ns = 0.f; int cv = 0;
    for (int i = tid; i < NROWS; i += 256) {
        if (g_valid[i]) { ps += g_rowpos[i]; ns += g_rowneg[i]; cv++; }
    }
    float q = 0.f;
    for (int i = tid; i < QBLKS; i += 256) q += g_qpart[i];
    // reductions
    #pragma unroll
    for (int o = 16; o > 0; o >>= 1) {
        ps += __shfl_xor_sync(0xFFFFFFFFu, ps, o);
        ns += __shfl_xor_sync(0xFFFFFFFFu, ns, o);
        cv += __shfl_xor_sync(0xFFFFFFFFu, cv, o);
        q  += __shfl_xor_sync(0xFFFFFFFFu, q, o);
    }
    if ((tid & 31) == 0) { scrF[tid >> 5] = ps; scrI[tid >> 5] = cv; }
    __syncthreads();
    __shared__ float scrF2[8]; __shared__ float scrF3[8];
    if ((tid & 31) == 0) { scrF2[tid >> 5] = ns; scrF3[tid >> 5] = q; }
    __syncthreads();
    if (tid == 0) {
        float psum = 0.f, nsum = 0.f, qs = 0.f; int cnt = 0;
        for (int w = 0; w < 8; w++) {
            psum += scrF[w]; nsum += scrF2[w]; qs += scrF3[w]; cnt += scrI[w];
        }
        float posL = (cnt > 0) ? psum / fmaxf((float)cnt, 1.f) : 0.f;
        float navL = (cnt > 0) ? nsum / fmaxf((float)cnt, 1.f) : 0.f;
        float ql = 0.1f * qs / (float)(NROWS * KDIM);
        out[0] = posL + navL + ql;
    }
}

extern "C" void kernel_launch(void* const* d_in, const int* in_sizes, int n_in,
                              void* d_out, int out_size) {
    const float* u = (const float*)d_in[0];
    const int*   y = (const int*)d_in[1];
    (void)in_sizes; (void)n_in; (void)out_size;

    cudaFuncSetAttribute(stats_loss_kernel,
                         cudaFuncAttributeMaxDynamicSharedMemorySize, SMEM_BYTES);

    tanh_kernel<<<QBLKS, 256>>>(u);
    label_kernel<<<(NROWS + 255) / 256, 256>>>(y);
    stats_loss_kernel<<<NBLK, NTHR, SMEM_BYTES>>>();
    final_kernel<<<1, 256>>>((float*)d_out);
}